// round 2
// baseline (speedup 1.0000x reference)
#include <cuda_runtime.h>

// ---------------------------------------------------------------------------
// Problem constants
// ---------------------------------------------------------------------------
#define BATCH 16
#define TLEN  4096
#define NTOK  (BATCH * TLEN)   // 65536 tokens
#define DDIM  512              // z / z_out feature dim
#define EDIM  256              // latent dim
#define NCODE 1024             // codebook entries

// Output packing (single f32 buffer): z_out | commitment[16] | codebook[16] | code[65536]
#define OFF_ZOUT 0
#define N_ZOUT   ((size_t)NTOK * DDIM)            // 33554432
#define OFF_L1   (N_ZOUT)
#define OFF_L2   (N_ZOUT + 16)
#define OFF_CODE (N_ZOUT + 32)
#define OUT_FULL (N_ZOUT + 32 + NTOK)             // 33620000

// ---------------------------------------------------------------------------
// Device scratch (static globals — no allocation allowed)
// ---------------------------------------------------------------------------
__device__ float g_wdT[DDIM * EDIM];     // w_down transposed: [k][e]
__device__ float g_cbT[EDIM * NCODE];    // codebook transposed: [e][j]
__device__ float g_cnh[NCODE];           // 0.5 * ||c_j||^2
__device__ float g_M[NCODE * DDIM];      // M = codebook @ w_up^T  (z_out gather table)
__device__ float g_partial[NTOK / 64];   // per-CTA partial loss sums (1024)

// ---------------------------------------------------------------------------
// Prep kernels
// ---------------------------------------------------------------------------
__global__ void k_prep_wdT(const float* __restrict__ wd) {
    int idx = blockIdx.x * 256 + threadIdx.x;        // 131072 total
    int k = idx >> 8, e = idx & 255;
    g_wdT[idx] = wd[e * DDIM + k];
}

__global__ void k_prep_cbT(const float* __restrict__ cb) {
    int idx = blockIdx.x * 256 + threadIdx.x;        // 262144 total
    int e = idx >> 10, j = idx & 1023;
    g_cbT[idx] = cb[j * EDIM + e];
}

__global__ void k_prep_cnh(const float* __restrict__ cb) {
    int j = blockIdx.x * 256 + threadIdx.x;
    if (j < NCODE) {
        const float4* r = (const float4*)(cb + (size_t)j * EDIM);
        float s = 0.f;
#pragma unroll 8
        for (int q = 0; q < EDIM / 4; q++) {
            float4 v = r[q];
            s += v.x * v.x + v.y * v.y + v.z * v.z + v.w * v.w;
        }
        g_cnh[j] = 0.5f * s;
    }
}

// M[j][d] = sum_e cb[j][e] * w_up[d][e]   (tile 8j x 32d per block, 2048 blocks)
__global__ void k_prep_M(const float* __restrict__ cb, const float* __restrict__ wu) {
    __shared__ float scb[8 * 256];
    __shared__ float swuT[256][33];
    int tid = threadIdx.x;
    int j0 = (blockIdx.x >> 4) * 8;
    int d0 = (blockIdx.x & 15) * 32;
#pragma unroll
    for (int r = 0; r < 2; r++) {
        int idx = tid + r * 256;                  // 512 float4
        int row = idx >> 6, q = (idx & 63) << 2;
        *(float4*)&scb[row * 256 + q] = *(const float4*)&cb[(size_t)(j0 + row) * EDIM + q];
    }
#pragma unroll
    for (int r = 0; r < 8; r++) {
        int idx = tid + r * 256;                  // 2048 float4
        int row = idx >> 6, q = (idx & 63) << 2;
        float4 v = *(const float4*)&wu[(size_t)(d0 + row) * EDIM + q];
        swuT[q + 0][row] = v.x; swuT[q + 1][row] = v.y;
        swuT[q + 2][row] = v.z; swuT[q + 3][row] = v.w;
    }
    __syncthreads();
    int jl = tid >> 5, dl = tid & 31;
    float s = 0.f;
#pragma unroll 8
    for (int e = 0; e < 256; e++) s += scb[jl * 256 + e] * swuT[e][dl];
    g_M[(size_t)(j0 + jl) * DDIM + d0 + dl] = s;
}

// ---------------------------------------------------------------------------
// Main fused kernel: 64 tokens per CTA, 256 threads, 8x8 register tiles.
//   Phase 1: z_e[64,256] = z_tile @ w_down^T        (smem-resident result)
//   Phase 2: scores vs 1024 codes, running argmin   (codebook via g_cbT, L2)
//   Epilogue: z_out gather from g_M, exact loss recompute, code write
// ---------------------------------------------------------------------------
__global__ __launch_bounds__(256, 2) void vq_main(
    const float* __restrict__ z, const float* __restrict__ cb,
    float* __restrict__ out, int write_extra)
{
    extern __shared__ float sm[];
    float* zesm = sm;                    // [64][256]  64 KB, persists all phases
    float* zt   = sm + 16384;            // [64][32]   phase-1 staging
    float* wsm  = sm + 16384 + 2048;     // [32][256]  phase-1 staging
    float* cbsm = sm + 16384;            // [32][256]  phase-2 staging (overlaps zt/wsm)
    __shared__ int   scode[64];
    __shared__ float sdist[64];

    const int tid = threadIdx.x;
    const int tx = tid & 31, ty = tid >> 5;
    const int tok0 = blockIdx.x * 64;

    float acc[8][8];
#pragma unroll
    for (int i = 0; i < 8; i++)
#pragma unroll
        for (int j = 0; j < 8; j++) acc[i][j] = 0.f;

    // ---------------- Phase 1: z_e = z @ w_down^T ----------------
    for (int kc = 0; kc < DDIM; kc += 32) {
#pragma unroll
        for (int r = 0; r < 2; r++) {
            int idx = tid + r * 256;              // 512 float4 (64x32 tile)
            int t = idx >> 3, q = (idx & 7) << 2;
            *(float4*)&zt[t * 32 + q] =
                *(const float4*)&z[(size_t)(tok0 + t) * DDIM + kc + q];
        }
#pragma unroll
        for (int r = 0; r < 8; r++) {
            int idx = tid + r * 256;              // 2048 float4 (32x256 tile)
            int row = idx >> 6, q = (idx & 63) << 2;
            *(float4*)&wsm[row * 256 + q] = *(const float4*)&g_wdT[(size_t)(kc + row) * EDIM + q];
        }
        __syncthreads();
#pragma unroll
        for (int kk = 0; kk < 32; kk += 4) {
            float4 a4[8];
#pragma unroll
            for (int i = 0; i < 8; i++)
                a4[i] = *(float4*)&zt[(ty * 8 + i) * 32 + kk];
#pragma unroll
            for (int u = 0; u < 4; u++) {
                float4 b0 = *(float4*)&wsm[(kk + u) * 256 + tx * 8];
                float4 b1 = *(float4*)&wsm[(kk + u) * 256 + tx * 8 + 4];
#pragma unroll
                for (int i = 0; i < 8; i++) {
                    float av = (u == 0) ? a4[i].x : (u == 1) ? a4[i].y
                             : (u == 2) ? a4[i].z : a4[i].w;
                    acc[i][0] += av * b0.x; acc[i][1] += av * b0.y;
                    acc[i][2] += av * b0.z; acc[i][3] += av * b0.w;
                    acc[i][4] += av * b1.x; acc[i][5] += av * b1.y;
                    acc[i][6] += av * b1.z; acc[i][7] += av * b1.w;
                }
            }
        }
        __syncthreads();
    }
#pragma unroll
    for (int i = 0; i < 8; i++) {
        *(float4*)&zesm[(ty * 8 + i) * 256 + tx * 8] =
            make_float4(acc[i][0], acc[i][1], acc[i][2], acc[i][3]);
        *(float4*)&zesm[(ty * 8 + i) * 256 + tx * 8 + 4] =
            make_float4(acc[i][4], acc[i][5], acc[i][6], acc[i][7]);
    }
    __syncthreads();

    // ---------------- Phase 2: nearest codebook entry ----------------
    float minv[8]; int mini[8];
#pragma unroll
    for (int i = 0; i < 8; i++) { minv[i] = 3.4e38f; mini[i] = 0; }

    for (int jc = 0; jc < 4; jc++) {                 // 4 chunks of 256 codes
#pragma unroll
        for (int i = 0; i < 8; i++)
#pragma unroll
            for (int j = 0; j < 8; j++) acc[i][j] = 0.f;

        for (int ec = 0; ec < EDIM; ec += 32) {
#pragma unroll
            for (int r = 0; r < 8; r++) {
                int idx = tid + r * 256;
                int row = idx >> 6, q = (idx & 63) << 2;
                *(float4*)&cbsm[row * 256 + q] =
                    *(const float4*)&g_cbT[(size_t)(ec + row) * NCODE + jc * 256 + q];
            }
            __syncthreads();
#pragma unroll
            for (int ee = 0; ee < 32; ee += 4) {
                float4 a4[8];
#pragma unroll
                for (int i = 0; i < 8; i++)
                    a4[i] = *(float4*)&zesm[(ty * 8 + i) * 256 + ec + ee];
#pragma unroll
                for (int u = 0; u < 4; u++) {
                    float4 b0 = *(float4*)&cbsm[(ee + u) * 256 + tx * 8];
                    float4 b1 = *(float4*)&cbsm[(ee + u) * 256 + tx * 8 + 4];
#pragma unroll
                    for (int i = 0; i < 8; i++) {
                        float av = (u == 0) ? a4[i].x : (u == 1) ? a4[i].y
                                 : (u == 2) ? a4[i].z : a4[i].w;
                        acc[i][0] += av * b0.x; acc[i][1] += av * b0.y;
                        acc[i][2] += av * b0.z; acc[i][3] += av * b0.w;
                        acc[i][4] += av * b1.x; acc[i][5] += av * b1.y;
                        acc[i][6] += av * b1.z; acc[i][7] += av * b1.w;
                    }
                }
            }
            __syncthreads();
        }
        float cn[8];
#pragma unroll
        for (int j = 0; j < 8; j++) cn[j] = g_cnh[jc * 256 + tx * 8 + j];
#pragma unroll
        for (int i = 0; i < 8; i++)
#pragma unroll
            for (int j = 0; j < 8; j++) {
                float s = cn[j] - acc[i][j];         // 0.5||c||^2 - z_e.c  (argmin-equivalent)
                if (s < minv[i]) { minv[i] = s; mini[i] = jc * 256 + tx * 8 + j; }
            }
    }

    // warp-level argmin reduce (lanes == tx), tie -> lower index (matches argmin)
#pragma unroll
    for (int i = 0; i < 8; i++) {
        float v = minv[i]; int id = mini[i];
#pragma unroll
        for (int off = 16; off > 0; off >>= 1) {
            float ov = __shfl_down_sync(0xffffffffu, v, off);
            int   oi = __shfl_down_sync(0xffffffffu, id, off);
            if (ov < v || (ov == v && oi < id)) { v = ov; id = oi; }
        }
        if (tx == 0) scode[ty * 8 + i] = id;
    }
    __syncthreads();

    // ---------------- Epilogue ----------------
    // z_out gather: out row = M[code]
#pragma unroll 4
    for (int idx = tid; idx < 64 * 128; idx += 256) {
        int t = idx >> 7, q = idx & 127;
        int c = scode[t];
        float4 v = *(const float4*)&g_M[(size_t)c * DDIM + q * 4];
        *(float4*)&out[(size_t)(tok0 + t) * DDIM + q * 4] = v;
    }

    // exact loss recompute: ||c - z_e||^2, 4 threads per token
    {
        int t = tid >> 2, sub = tid & 3;
        int c = scode[t];
        const float* crow = cb + (size_t)c * EDIM;
        float ls = 0.f;
#pragma unroll 4
        for (int q = sub * 16; q < sub * 16 + 16; q++) {
            float4 cv = *(const float4*)&crow[q * 4];
            float4 zv = *(float4*)&zesm[t * 256 + q * 4];
            float d0 = cv.x - zv.x, d1 = cv.y - zv.y;
            float d2 = cv.z - zv.z, d3 = cv.w - zv.w;
            ls += d0 * d0 + d1 * d1 + d2 * d2 + d3 * d3;
        }
        ls += __shfl_xor_sync(0xffffffffu, ls, 1);
        ls += __shfl_xor_sync(0xffffffffu, ls, 2);
        if (sub == 0) sdist[t] = ls;
    }
    __syncthreads();
    if (tid == 0) {                                  // deterministic ordered sum
        float s = 0.f;
        for (int t = 0; t < 64; t++) s += sdist[t];
        g_partial[blockIdx.x] = s;
    }
    if (write_extra && tid < 64)
        out[OFF_CODE + tok0 + tid] = (float)scode[tid];
}

__global__ void k_finalize(float* __restrict__ out) {
    int b = threadIdx.x;
    if (b < BATCH) {
        float s = 0.f;
        for (int i = 0; i < 64; i++) s += g_partial[b * 64 + i];  // fixed order
        float loss = s * (1.0f / ((float)TLEN * (float)EDIM));
        out[OFF_L1 + b] = loss;
        out[OFF_L2 + b] = loss;
    }
}

// ---------------------------------------------------------------------------
extern "C" void kernel_launch(void* const* d_in, const int* in_sizes, int n_in,
                              void* d_out, int out_size) {
    const float* z  = (const float*)d_in[0];
    const float* cb = (const float*)d_in[1];
    const float* wd = (const float*)d_in[2];
    const float* wu = (const float*)d_in[3];
    float* out = (float*)d_out;

    int write_extra = ((size_t)out_size >= OUT_FULL) ? 1 : 0;

    cudaFuncSetAttribute(vq_main, cudaFuncAttributeMaxDynamicSharedMemorySize, 106496);

    k_prep_wdT<<<512, 256>>>(wd);
    k_prep_cbT<<<1024, 256>>>(cb);
    k_prep_cnh<<<4, 256>>>(cb);
    k_prep_M<<<2048, 256>>>(cb, wu);
    vq_main<<<NTOK / 64, 256, 106496>>>(z, cb, out, write_extra);
    if (write_extra) k_finalize<<<1, 32>>>(out);
}

// round 3
// speedup vs baseline: 1.9321x; 1.9321x over previous
#include <cuda_runtime.h>

// ---------------------------------------------------------------------------
// Problem constants
// ---------------------------------------------------------------------------
#define BATCH 16
#define TLEN  4096
#define NTOK  (BATCH * TLEN)   // 65536 tokens
#define DDIM  512              // z / z_out feature dim
#define EDIM  256              // latent dim
#define NCODE 1024             // codebook entries

// Output packing (single f32 buffer): z_out | commitment[16] | codebook[16] | code[65536]
#define N_ZOUT   ((size_t)NTOK * DDIM)            // 33554432
#define OFF_L1   (N_ZOUT)
#define OFF_L2   (N_ZOUT + 16)
#define OFF_CODE (N_ZOUT + 32)
#define OUT_FULL (N_ZOUT + 32 + NTOK)             // 33620000

typedef unsigned long long u64;

// ---------------------------------------------------------------------------
// Packed f32x2 helpers (FFMA2 path — only reachable via PTX)
// ---------------------------------------------------------------------------
__device__ __forceinline__ u64 pack2(float x, float y) {
    u64 r; asm("mov.b64 %0, {%1, %2};" : "=l"(r) : "f"(x), "f"(y)); return r;
}
__device__ __forceinline__ float2 unpack2(u64 v) {
    float2 r; asm("mov.b64 {%0, %1}, %2;" : "=f"(r.x), "=f"(r.y) : "l"(v)); return r;
}
__device__ __forceinline__ void fma2(u64& d, u64 a, u64 b) {
    asm("fma.rn.f32x2 %0, %1, %2, %0;" : "+l"(d) : "l"(a), "l"(b));
}

// ---------------------------------------------------------------------------
// Device scratch (static globals — no allocation allowed)
// ---------------------------------------------------------------------------
__device__ float g_wdT[DDIM * EDIM];     // w_down transposed: [k][e]
__device__ float g_cbT[EDIM * NCODE];    // codebook transposed: [e][j]
__device__ float g_cnh[NCODE];           // 0.5 * ||c_j||^2
__device__ float g_M[NCODE * DDIM];      // M = codebook @ w_up^T  (z_out gather table)
__device__ float g_partial[NTOK / 64];   // per-CTA partial loss sums (1024)

// ---------------------------------------------------------------------------
// Prep kernels
// ---------------------------------------------------------------------------
__global__ void k_prep_wdT(const float* __restrict__ wd) {
    int idx = blockIdx.x * 256 + threadIdx.x;        // 131072 total
    int k = idx >> 8, e = idx & 255;
    g_wdT[idx] = wd[e * DDIM + k];
}

__global__ void k_prep_cbT(const float* __restrict__ cb) {
    int idx = blockIdx.x * 256 + threadIdx.x;        // 262144 total
    int e = idx >> 10, j = idx & 1023;
    g_cbT[idx] = cb[j * EDIM + e];
}

__global__ void k_prep_cnh(const float* __restrict__ cb) {
    int j = blockIdx.x * 256 + threadIdx.x;
    if (j < NCODE) {
        const float4* r = (const float4*)(cb + (size_t)j * EDIM);
        float s = 0.f;
#pragma unroll 8
        for (int q = 0; q < EDIM / 4; q++) {
            float4 v = r[q];
            s += v.x * v.x + v.y * v.y + v.z * v.z + v.w * v.w;
        }
        g_cnh[j] = 0.5f * s;
    }
}

// M[j][d] = sum_e cb[j][e] * w_up[d][e]   (tile 8j x 32d per block, 2048 blocks)
__global__ void k_prep_M(const float* __restrict__ cb, const float* __restrict__ wu) {
    __shared__ float scb[8 * 256];
    __shared__ float swuT[256][33];
    int tid = threadIdx.x;
    int j0 = (blockIdx.x >> 4) * 8;
    int d0 = (blockIdx.x & 15) * 32;
#pragma unroll
    for (int r = 0; r < 2; r++) {
        int idx = tid + r * 256;                  // 512 float4
        int row = idx >> 6, q = (idx & 63) << 2;
        *(float4*)&scb[row * 256 + q] = *(const float4*)&cb[(size_t)(j0 + row) * EDIM + q];
    }
#pragma unroll
    for (int r = 0; r < 8; r++) {
        int idx = tid + r * 256;                  // 2048 float4
        int row = idx >> 6, q = (idx & 63) << 2;
        float4 v = *(const float4*)&wu[(size_t)(d0 + row) * EDIM + q];
        swuT[q + 0][row] = v.x; swuT[q + 1][row] = v.y;
        swuT[q + 2][row] = v.z; swuT[q + 3][row] = v.w;
    }
    __syncthreads();
    int jl = tid >> 5, dl = tid & 31;
    float s = 0.f;
#pragma unroll 8
    for (int e = 0; e < 256; e++) s += scb[jl * 256 + e] * swuT[e][dl];
    g_M[(size_t)(j0 + jl) * DDIM + d0 + dl] = s;
}

// ---------------------------------------------------------------------------
// Main fused kernel: 64 tokens per CTA, 256 threads, 8x8 register tiles,
// packed f32x2 FMA, conflict-free smem column mapping:
//   thread (tx) owns output columns {tx*4..tx*4+3} and {128+tx*4..128+tx*4+3}
// ---------------------------------------------------------------------------
__global__ __launch_bounds__(256, 2) void vq_main(
    const float* __restrict__ z, const float* __restrict__ cb,
    float* __restrict__ out, int write_extra)
{
    extern __shared__ float sm[];
    float* zesm = sm;                    // [64][256]  64 KB, persists all phases
    float* zt   = sm + 16384;            // [64][32]   phase-1 staging
    float* wsm  = sm + 16384 + 2048;     // [32][256]  phase-1 staging
    float* cbsm = sm + 16384;            // [32][256]  phase-2 staging (overlaps zt/wsm)
    __shared__ int   scode[64];
    __shared__ float sdist[64];

    const int tid = threadIdx.x;
    const int tx = tid & 31, ty = tid >> 5;
    const int tok0 = blockIdx.x * 64;

    u64 acc[8][4];                       // [token i][col-pair g]: g=0,1 -> e=tx*4+{0,1},{2,3}; g=2,3 -> e=128+tx*4+{0,1},{2,3}
#pragma unroll
    for (int i = 0; i < 8; i++)
#pragma unroll
        for (int g = 0; g < 4; g++) acc[i][g] = 0ULL;

    // ---------------- Phase 1: z_e = z @ w_down^T ----------------
    for (int kc = 0; kc < DDIM; kc += 32) {
#pragma unroll
        for (int r = 0; r < 2; r++) {
            int idx = tid + r * 256;              // 512 float4 (64x32 tile)
            int t = idx >> 3, q = (idx & 7) << 2;
            *(float4*)&zt[t * 32 + q] =
                *(const float4*)&z[(size_t)(tok0 + t) * DDIM + kc + q];
        }
#pragma unroll
        for (int r = 0; r < 8; r++) {
            int idx = tid + r * 256;              // 2048 float4 (32x256 tile)
            int row = idx >> 6, q = (idx & 63) << 2;
            *(float4*)&wsm[row * 256 + q] = *(const float4*)&g_wdT[(size_t)(kc + row) * EDIM + q];
        }
        __syncthreads();
#pragma unroll
        for (int kk = 0; kk < 32; kk += 4) {
            float4 a4[8];
#pragma unroll
            for (int i = 0; i < 8; i++)
                a4[i] = *(float4*)&zt[(ty * 8 + i) * 32 + kk];
#pragma unroll
            for (int u = 0; u < 4; u++) {
                ulonglong2 b0 = *(const ulonglong2*)&wsm[(kk + u) * 256 + tx * 4];
                ulonglong2 b1 = *(const ulonglong2*)&wsm[(kk + u) * 256 + 128 + tx * 4];
#pragma unroll
                for (int i = 0; i < 8; i++) {
                    float av = (u == 0) ? a4[i].x : (u == 1) ? a4[i].y
                             : (u == 2) ? a4[i].z : a4[i].w;
                    u64 av2 = pack2(av, av);
                    fma2(acc[i][0], av2, b0.x); fma2(acc[i][1], av2, b0.y);
                    fma2(acc[i][2], av2, b1.x); fma2(acc[i][3], av2, b1.y);
                }
            }
        }
        __syncthreads();
    }
#pragma unroll
    for (int i = 0; i < 8; i++) {
        ulonglong2 s0; s0.x = acc[i][0]; s0.y = acc[i][1];
        ulonglong2 s1; s1.x = acc[i][2]; s1.y = acc[i][3];
        *(ulonglong2*)&zesm[(ty * 8 + i) * 256 + tx * 4]       = s0;
        *(ulonglong2*)&zesm[(ty * 8 + i) * 256 + 128 + tx * 4] = s1;
    }
    __syncthreads();

    // ---------------- Phase 2: nearest codebook entry ----------------
    float minv[8]; int mini[8];
#pragma unroll
    for (int i = 0; i < 8; i++) { minv[i] = 3.4e38f; mini[i] = 0; }

    for (int jc = 0; jc < 4; jc++) {                 // 4 chunks of 256 codes
#pragma unroll
        for (int i = 0; i < 8; i++)
#pragma unroll
            for (int g = 0; g < 4; g++) acc[i][g] = 0ULL;

        for (int ec = 0; ec < EDIM; ec += 32) {
#pragma unroll
            for (int r = 0; r < 8; r++) {
                int idx = tid + r * 256;
                int row = idx >> 6, q = (idx & 63) << 2;
                *(float4*)&cbsm[row * 256 + q] =
                    *(const float4*)&g_cbT[(size_t)(ec + row) * NCODE + jc * 256 + q];
            }
            __syncthreads();
#pragma unroll
            for (int ee = 0; ee < 32; ee += 4) {
                float4 a4[8];
#pragma unroll
                for (int i = 0; i < 8; i++)
                    a4[i] = *(float4*)&zesm[(ty * 8 + i) * 256 + ec + ee];
#pragma unroll
                for (int u = 0; u < 4; u++) {
                    ulonglong2 b0 = *(const ulonglong2*)&cbsm[(ee + u) * 256 + tx * 4];
                    ulonglong2 b1 = *(const ulonglong2*)&cbsm[(ee + u) * 256 + 128 + tx * 4];
#pragma unroll
                    for (int i = 0; i < 8; i++) {
                        float av = (u == 0) ? a4[i].x : (u == 1) ? a4[i].y
                                 : (u == 2) ? a4[i].z : a4[i].w;
                        u64 av2 = pack2(av, av);
                        fma2(acc[i][0], av2, b0.x); fma2(acc[i][1], av2, b0.y);
                        fma2(acc[i][2], av2, b1.x); fma2(acc[i][3], av2, b1.y);
                    }
                }
            }
            __syncthreads();
        }
        // columns this thread owns in this chunk:
        //   g=0: j = jc*256 + tx*4 + {0,1}        g=1: + {2,3}
        //   g=2: j = jc*256 + 128 + tx*4 + {0,1}  g=3: + {2,3}
        int jb0 = jc * 256 + tx * 4;
        int jb1 = jc * 256 + 128 + tx * 4;
        float cn[8];
#pragma unroll
        for (int q = 0; q < 4; q++) { cn[q] = g_cnh[jb0 + q]; cn[4 + q] = g_cnh[jb1 + q]; }
#pragma unroll
        for (int i = 0; i < 8; i++) {
#pragma unroll
            for (int g = 0; g < 4; g++) {
                float2 s = unpack2(acc[i][g]);
                int jlo = (g < 2) ? (jb0 + (g & 1) * 2) : (jb1 + (g & 1) * 2);
                float c0 = cn[(g < 2 ? 0 : 4) + (g & 1) * 2];
                float c1 = cn[(g < 2 ? 0 : 4) + (g & 1) * 2 + 1];
                float d0 = c0 - s.x;                 // 0.5||c||^2 - z_e.c
                float d1 = c1 - s.y;
                if (d0 < minv[i]) { minv[i] = d0; mini[i] = jlo; }
                if (d1 < minv[i]) { minv[i] = d1; mini[i] = jlo + 1; }
            }
        }
    }

    // warp-level argmin reduce (lanes == tx), tie -> lower index (matches argmin)
#pragma unroll
    for (int i = 0; i < 8; i++) {
        float v = minv[i]; int id = mini[i];
#pragma unroll
        for (int off = 16; off > 0; off >>= 1) {
            float ov = __shfl_down_sync(0xffffffffu, v, off);
            int   oi = __shfl_down_sync(0xffffffffu, id, off);
            if (ov < v || (ov == v && oi < id)) { v = ov; id = oi; }
        }
        if (tx == 0) scode[ty * 8 + i] = id;
    }
    __syncthreads();

    // ---------------- Epilogue ----------------
    // z_out gather: out row = M[code]
#pragma unroll 4
    for (int idx = tid; idx < 64 * 128; idx += 256) {
        int t = idx >> 7, q = idx & 127;
        int c = scode[t];
        float4 v = *(const float4*)&g_M[(size_t)c * DDIM + q * 4];
        *(float4*)&out[(size_t)(tok0 + t) * DDIM + q * 4] = v;
    }

    // exact loss recompute: ||c - z_e||^2, 4 threads per token
    // (qi rotated by t to break the 8-way bank conflict on zesm reads)
    {
        int t = tid >> 2, sub = tid & 3;
        int c = scode[t];
        const float* crow = cb + (size_t)c * EDIM;
        float ls = 0.f;
#pragma unroll 4
        for (int k = 0; k < 16; k++) {
            int q = sub * 16 + ((k + t) & 15);
            float4 cv = *(const float4*)&crow[q * 4];
            float4 zv = *(float4*)&zesm[t * 256 + q * 4];
            float d0 = cv.x - zv.x, d1 = cv.y - zv.y;
            float d2 = cv.z - zv.z, d3 = cv.w - zv.w;
            ls += d0 * d0 + d1 * d1 + d2 * d2 + d3 * d3;
        }
        ls += __shfl_xor_sync(0xffffffffu, ls, 1);
        ls += __shfl_xor_sync(0xffffffffu, ls, 2);
        if (sub == 0) sdist[t] = ls;
    }
    __syncthreads();
    if (tid == 0) {                                  // deterministic ordered sum
        float s = 0.f;
        for (int t = 0; t < 64; t++) s += sdist[t];
        g_partial[blockIdx.x] = s;
    }
    if (write_extra && tid < 64)
        out[OFF_CODE + tok0 + tid] = (float)scode[tid];
}

__global__ void k_finalize(float* __restrict__ out) {
    int b = threadIdx.x;
    if (b < BATCH) {
        float s = 0.f;
        for (int i = 0; i < 64; i++) s += g_partial[b * 64 + i];  // fixed order
        float loss = s * (1.0f / ((float)TLEN * (float)EDIM));
        out[OFF_L1 + b] = loss;
        out[OFF_L2 + b] = loss;
    }
}

// ---------------------------------------------------------------------------
extern "C" void kernel_launch(void* const* d_in, const int* in_sizes, int n_in,
                              void* d_out, int out_size) {
    const float* z  = (const float*)d_in[0];
    const float* cb = (const float*)d_in[1];
    const float* wd = (const float*)d_in[2];
    const float* wu = (const float*)d_in[3];
    float* out = (float*)d_out;

    int write_extra = ((size_t)out_size >= OUT_FULL) ? 1 : 0;

    cudaFuncSetAttribute(vq_main, cudaFuncAttributeMaxDynamicSharedMemorySize, 106496);

    k_prep_wdT<<<512, 256>>>(wd);
    k_prep_cbT<<<1024, 256>>>(cb);
    k_prep_cnh<<<4, 256>>>(cb);
    k_prep_M<<<2048, 256>>>(cb, wu);
    vq_main<<<NTOK / 64, 256, 106496>>>(z, cb, out, write_extra);
    if (write_extra) k_finalize<<<1, 32>>>(out);
}